// round 12
// baseline (speedup 1.0000x reference)
#include <cuda_runtime.h>
#include <cuda_bf16.h>
#include <math.h>
#include <stddef.h>
#include <stdint.h>

#define B_   32
#define S_   512
#define E_   512
#define INNER_ 1024
#define NH_  4
#define DH_  256
#define M_TOK (B_*S_)   // 16384
#define HALF_B (B_/2)   // 16

// ---------------- scratch (device globals: allocation-free) ----------------
__device__ __nv_bfloat16 g_hb[(size_t)M_TOK*E_];   // LN'd embeddings, bf16 (16 MB)
__device__ __nv_bfloat16 g_wtb[(size_t)INNER_*E_]; // w_up first half, bf16 (1 MB)
__device__ float g_xm[(size_t)M_TOK*INNER_];     // up-proj first half   (64 MB)
__device__ float g_q[(size_t)B_*NH_*S_*DH_];     // q  [b][h][t][d]      (64 MB)
__device__ float g_k[(size_t)B_*NH_*S_*DH_];     // k                    (64 MB)
__device__ float g_v[(size_t)B_*NH_*S_*DH_];     // v                    (64 MB)
__device__ float g_ig[B_*NH_*S_];
__device__ float g_lf[B_*NH_*S_];                // log_sigmoid(fg)
__device__ float g_hlast[B_*E_];                 // LN'd embedding at s=511 (fp32)
__device__ float g_res_last[B_*E_];
__device__ float g_xa_last[B_*INNER_];
__device__ float g_hs[B_*INNER_];

__device__ __forceinline__ float silu_f(float x) { return x / (1.f + expf(-x)); }

// MUFU-free silu: exp2-based e^x + Newton reciprocal
__device__ __forceinline__ float silu_fast(float x) {
    float t = x * 1.44269504f;
    int   ni = __float2int_rn(t);
    float r  = t - (float)ni;
    float p  = 0.0018775767f;
    p = p*r + 0.0089893397f;
    p = p*r + 0.055826318f;
    p = p*r + 0.24015361f;
    p = p*r + 0.69315308f;
    p = p*r + 1.0f;
    float ex = __int_as_float((ni + 127) << 23) * p;
    float d  = 1.f + ex;
    float rr = __int_as_float(0x7EF311C3 - __float_as_int(d));
    rr = rr*(2.f - d*rr);
    rr = rr*(2.f - d*rr);
    rr = rr*(2.f - d*rr);
    return x * ex * rr;
}

__device__ __forceinline__ void cp16(void* smem, const void* gmem) {
    uint32_t s = (uint32_t)__cvta_generic_to_shared(smem);
    asm volatile("cp.async.cg.shared.global [%0], [%1], 16;" :: "r"(s), "l"(gmem));
}

// ---------------- K0: convert w_up first half to bf16 ----------------
__global__ void k0_round_wup(const float* __restrict__ wup)
{
    int i = (blockIdx.x * 256 + threadIdx.x) * 4;
    float4 t = *(const float4*)&wup[i];
    g_wtb[i+0] = __float2bfloat16_rn(t.x);
    g_wtb[i+1] = __float2bfloat16_rn(t.y);
    g_wtb[i+2] = __float2bfloat16_rn(t.z);
    g_wtb[i+3] = __float2bfloat16_rn(t.w);
}

// ---------------- K1: embedding gather + LayerNorm (bf16 out for GEMM) ----------------
__global__ void k1_embed_ln(const int* __restrict__ tokens,
                            const float* __restrict__ emb,
                            const float* __restrict__ ln1w,
                            int m_off)
{
    int m = blockIdx.x + m_off;
    int tid = threadIdx.x;
    int tok = tokens[m];
    float x0 = 0.f, x1 = 0.f;
    if (tok != 0) {
        const float* row = emb + (size_t)tok * E_;
        x0 = row[tid];
        x1 = row[tid + 256];
    }
    __shared__ float red[256];
    red[tid] = x0 + x1;
    __syncthreads();
    for (int o = 128; o > 0; o >>= 1) { if (tid < o) red[tid] += red[tid+o]; __syncthreads(); }
    float mean = red[0] * (1.f / E_);
    __syncthreads();
    red[tid] = x0*x0 + x1*x1;
    __syncthreads();
    for (int o = 128; o > 0; o >>= 1) { if (tid < o) red[tid] += red[tid+o]; __syncthreads(); }
    float var = red[0] * (1.f / E_) - mean*mean;
    float rstd = rsqrtf(var + 1e-5f);

    float h0 = (x0 - mean) * rstd * ln1w[tid];
    float h1 = (x1 - mean) * rstd * ln1w[tid + 256];
    g_hb[(size_t)m*E_ + tid]       = __float2bfloat16_rn(h0);
    g_hb[(size_t)m*E_ + tid + 256] = __float2bfloat16_rn(h1);

    if ((m & (S_-1)) == S_-1) {
        int b = m >> 9;
        g_res_last[b*E_ + tid]       = x0;
        g_res_last[b*E_ + tid + 256] = x1;
        g_hlast[b*E_ + tid]       = h0;
        g_hlast[b*E_ + tid + 256] = h1;
    }
}

// ---------------- K2: up-projection GEMM via bf16 mma.sync + cp.async ----------------
#define TBM 128
#define TBN 128
#define NIT 16
#define STAGES 3
#define APITCH 20
#define TILE_U32 (TBM*APITCH)
#define K2_SMEM (STAGES*2*TILE_U32*4)

__global__ void __launch_bounds__(256) k2_gemm_up(int y_off)
{
    extern __shared__ uint32_t sm[];
    uint32_t* As = sm;
    uint32_t* Bs = sm + STAGES*TILE_U32;

    int tid  = threadIdx.x;
    int lane = tid & 31;
    int wid  = tid >> 5;
    int warp_m = wid & 1;
    int warp_n = wid >> 1;
    int g  = lane >> 2;
    int tg = lane & 3;

    int m0 = (blockIdx.y + y_off) * TBM;
    int n0 = blockIdx.x * TBN;

    float c[4][4][4];
    #pragma unroll
    for (int mt = 0; mt < 4; mt++)
        #pragma unroll
        for (int nt = 0; nt < 4; nt++)
            #pragma unroll
            for (int r = 0; r < 4; r++) c[mt][nt][r] = 0.f;

    #pragma unroll
    for (int p = 0; p < STAGES-1; p++) {
        #pragma unroll
        for (int j = 0; j < 2; j++) {
            int u = tid + j*256;
            int r = u >> 2, q = u & 3;
            cp16(&As[p*TILE_U32 + r*APITCH + q*4], &g_hb[(size_t)(m0+r)*E_ + p*32 + q*8]);
            cp16(&Bs[p*TILE_U32 + r*APITCH + q*4], &g_wtb[(size_t)(n0+r)*E_ + p*32 + q*8]);
        }
        asm volatile("cp.async.commit_group;");
    }

    for (int it = 0; it < NIT; it++) {
        int pf = it + STAGES - 1;
        if (pf < NIT) {
            int st = pf % STAGES;
            #pragma unroll
            for (int j = 0; j < 2; j++) {
                int u = tid + j*256;
                int r = u >> 2, q = u & 3;
                cp16(&As[st*TILE_U32 + r*APITCH + q*4], &g_hb[(size_t)(m0+r)*E_ + pf*32 + q*8]);
                cp16(&Bs[st*TILE_U32 + r*APITCH + q*4], &g_wtb[(size_t)(n0+r)*E_ + pf*32 + q*8]);
            }
        }
        asm volatile("cp.async.commit_group;");
        asm volatile("cp.async.wait_group %0;" :: "n"(STAGES-1));
        __syncthreads();

        const uint32_t* Ab = &As[(it % STAGES)*TILE_U32];
        const uint32_t* Bb = &Bs[(it % STAGES)*TILE_U32];
        #pragma unroll
        for (int ks = 0; ks < 2; ks++) {
            int kb = ks * 8;
            uint32_t af[4][4], bf[4][2];
            #pragma unroll
            for (int mt = 0; mt < 4; mt++) {
                int row = warp_m*64 + mt*16 + g;
                af[mt][0] = Ab[row*APITCH + kb+tg];
                af[mt][1] = Ab[(row+8)*APITCH + kb+tg];
                af[mt][2] = Ab[row*APITCH + kb+tg+4];
                af[mt][3] = Ab[(row+8)*APITCH + kb+tg+4];
            }
            #pragma unroll
            for (int nt = 0; nt < 4; nt++) {
                int n = warp_n*32 + nt*8 + g;
                bf[nt][0] = Bb[n*APITCH + kb+tg];
                bf[nt][1] = Bb[n*APITCH + kb+tg+4];
            }
            #pragma unroll
            for (int mt = 0; mt < 4; mt++)
                #pragma unroll
                for (int nt = 0; nt < 4; nt++) {
                    asm volatile(
                        "mma.sync.aligned.m16n8k16.row.col.f32.bf16.bf16.f32 "
                        "{%0,%1,%2,%3}, {%4,%5,%6,%7}, {%8,%9}, {%0,%1,%2,%3};"
                        : "+f"(c[mt][nt][0]), "+f"(c[mt][nt][1]),
                          "+f"(c[mt][nt][2]), "+f"(c[mt][nt][3])
                        : "r"(af[mt][0]), "r"(af[mt][1]), "r"(af[mt][2]), "r"(af[mt][3]),
                          "r"(bf[nt][0]), "r"(bf[nt][1]));
                }
        }
        __syncthreads();
    }

    #pragma unroll
    for (int mt = 0; mt < 4; mt++) {
        int row = m0 + warp_m*64 + mt*16 + g;
        #pragma unroll
        for (int nt = 0; nt < 4; nt++) {
            int col = n0 + warp_n*32 + nt*8 + 2*tg;
            *(float2*)&g_xm[(size_t)row*INNER_ + col]     = make_float2(c[mt][nt][0], c[mt][nt][1]);
            *(float2*)&g_xm[(size_t)(row+8)*INNER_ + col] = make_float2(c[mt][nt][2], c[mt][nt][3]);
        }
    }
}

// ---------------- K3: causal conv + silu + block-diag q/k/v ----------------
__global__ void __launch_bounds__(256) k3_conv_qkv(
        const float* __restrict__ convw, const float* __restrict__ convb,
        const float* __restrict__ qw, const float* __restrict__ kw,
        const float* __restrict__ vw, int b_off)
{
    int t  = threadIdx.x;
    int b  = blockIdx.y + b_off;
    int s0 = blockIdx.x * 8;
    int c0 = blockIdx.z * 512 + 2*t;
    int qd = c0 >> 2;
    int hf = (c0 >> 1) & 1;

    float cw[2][4], cb2[2], qwr[2][4], kwr[2][4], vwr[2][4];
    #pragma unroll
    for (int o = 0; o < 2; o++) {
        int ch = c0 + o;
        int oq = hf*2 + o;
        cb2[o] = convb[ch];
        #pragma unroll
        for (int j = 0; j < 4; j++) cw[o][j] = convw[ch*4 + j];
        #pragma unroll
        for (int i = 0; i < 4; i++) {
            qwr[o][i] = qw[qd*16 + oq*4 + i];
            kwr[o][i] = kw[qd*16 + oq*4 + i];
            vwr[o][i] = vw[qd*16 + oq*4 + i];
        }
    }

    float win[4][2];
    #pragma unroll
    for (int j = 0; j < 3; j++) {
        int s = s0 - 3 + j;
        if (s >= 0) {
            float2 xm = *(const float2*)&g_xm[((size_t)b*S_ + s)*INNER_ + c0];
            win[j][0] = xm.x; win[j][1] = xm.y;
        } else { win[j][0] = 0.f; win[j][1] = 0.f; }
    }

    int h  = c0 >> 8;
    int dd = c0 & 255;

    for (int ss = 0; ss < 8; ss++) {
        int s = s0 + ss;
        float2 xm = *(const float2*)&g_xm[((size_t)b*S_ + s)*INNER_ + c0];
        win[3][0] = xm.x; win[3][1] = xm.y;

        float xa0, xa1;
        {
            float a0 = cb2[0], a1 = cb2[1];
            #pragma unroll
            for (int j = 0; j < 4; j++) { a0 += win[j][0]*cw[0][j]; a1 += win[j][1]*cw[1][j]; }
            xa0 = silu_fast(a0); xa1 = silu_fast(a1);
        }
        float pxa0 = __shfl_xor_sync(0xffffffffu, xa0, 1);
        float pxa1 = __shfl_xor_sync(0xffffffffu, xa1, 1);
        float pxm0 = __shfl_xor_sync(0xffffffffu, xm.x, 1);
        float pxm1 = __shfl_xor_sync(0xffffffffu, xm.y, 1);

        float xaq[4], xmq[4];
        if (hf == 0) {
            xaq[0]=xa0;  xaq[1]=xa1;  xaq[2]=pxa0; xaq[3]=pxa1;
            xmq[0]=xm.x; xmq[1]=xm.y; xmq[2]=pxm0; xmq[3]=pxm1;
        } else {
            xaq[0]=pxa0; xaq[1]=pxa1; xaq[2]=xa0;  xaq[3]=xa1;
            xmq[0]=pxm0; xmq[1]=pxm1; xmq[2]=xm.x; xmq[3]=xm.y;
        }

        float qv[2], kv[2], vv[2];
        #pragma unroll
        for (int o = 0; o < 2; o++) {
            float a = 0.f, bk = 0.f, c2 = 0.f;
            #pragma unroll
            for (int i = 0; i < 4; i++) {
                a  += xaq[i]*qwr[o][i];
                bk += xaq[i]*kwr[o][i];
                c2 += xmq[i]*vwr[o][i];
            }
            qv[o] = a; kv[o] = bk; vv[o] = c2;
        }
        size_t base = (((size_t)b*NH_ + h)*S_ + s)*DH_ + dd;
        *(float2*)&g_q[base] = make_float2(qv[0], qv[1]);
        *(float2*)&g_k[base] = make_float2(kv[0], kv[1]);
        *(float2*)&g_v[base] = make_float2(vv[0], vv[1]);
        if (s == S_-1)
            *(float2*)&g_xa_last[b*INNER_ + c0] = make_float2(xa0, xa1);

        #pragma unroll
        for (int o = 0; o < 2; o++) { win[0][o]=win[1][o]; win[1][o]=win[2][o]; win[2][o]=win[3][o]; }
    }
}

// ---------------- K3b: ig/fg gates, float4-vectorized ----------------
__global__ void k3b_gates(const float* __restrict__ igw, const float* __restrict__ igb,
                          const float* __restrict__ fgw, const float* __restrict__ fgb,
                          int b_off)
{
    int tid = threadIdx.x;
    int lane = tid & 31, w = tid >> 5;
    int blk = blockIdx.x;
    int b = (blk >> 4) + b_off;
    int t0 = (blk & 15) * 32 + w * 4;

    float aI[4][4], aF[4][4];
    #pragma unroll
    for (int r = 0; r < 4; r++)
        #pragma unroll
        for (int g = 0; g < 4; g++) { aI[r][g] = 0.f; aF[r][g] = 0.f; }

    const float* segp[3] = { g_q, g_k, g_v };
    #pragma unroll
    for (int seg = 0; seg < 3; seg++) {
        const float* P = segp[seg];
        #pragma unroll
        for (int c0 = 0; c0 < INNER_; c0 += 128) {
            int cw_ = c0 + lane*4;
            int hh = cw_ >> 8, dd = cw_ & 255;
            float4 wI4[4], wF4[4];
            #pragma unroll
            for (int g = 0; g < 4; g++) {
                wI4[g] = *(const float4*)&igw[g*3072 + seg*1024 + cw_];
                wF4[g] = *(const float4*)&fgw[g*3072 + seg*1024 + cw_];
            }
            size_t rb = (((size_t)b*NH_ + hh)*S_ + t0)*DH_ + dd;
            #pragma unroll
            for (int r = 0; r < 4; r++) {
                float4 val = *(const float4*)&P[rb + (size_t)r*DH_];
                #pragma unroll
                for (int g = 0; g < 4; g++) {
                    aI[r][g] += val.x*wI4[g].x + val.y*wI4[g].y + val.z*wI4[g].z + val.w*wI4[g].w;
                    aF[r][g] += val.x*wF4[g].x + val.y*wF4[g].y + val.z*wF4[g].z + val.w*wF4[g].w;
                }
            }
        }
    }
    #pragma unroll
    for (int r = 0; r < 4; r++) {
        #pragma unroll
        for (int g = 0; g < 4; g++) {
            float sI = aI[r][g], sF = aF[r][g];
            #pragma unroll
            for (int o = 16; o > 0; o >>= 1) {
                sI += __shfl_xor_sync(0xffffffffu, sI, o);
                sF += __shfl_xor_sync(0xffffffffu, sF, o);
            }
            if (lane == 0) {
                int t = t0 + r;
                g_ig[(b*NH_+g)*S_ + t] = sI + igb[g];
                float fgv = sF + fgb[g];
                float lf = (fgv >= 0.f) ? -log1pf(expf(-fgv)) : (fgv - log1pf(expf(fgv)));
                g_lf[(b*NH_+g)*S_ + t] = lf;
            }
        }
    }
}

// ---------------- K4: mLSTM last-row + head-LN + hs ----------------
__global__ void k4_mlstm(const float* __restrict__ wup, const float* __restrict__ onormw,
                         const float* __restrict__ skipw, int b_off)
{
    int tid = threadIdx.x;
    int lane = tid & 31, wrp = tid >> 5;
    int b = (blockIdx.x >> 2) + b_off, h = blockIdx.x & 3;
    size_t bh = (size_t)b*NH_ + h;

    __shared__ float s_q[DH_];
    __shared__ float s_w[S_];
    __shared__ float s_qk[S_];
    __shared__ float s_hr[E_];
    __shared__ float s_z[DH_];
    __shared__ float red[256];
    __shared__ float wtot[8], woff[8];

    s_q[tid] = g_q[(bh*S_ + (S_-1))*DH_ + tid];
    s_hr[tid]       = g_hlast[b*E_ + tid];
    s_hr[tid + 256] = g_hlast[b*E_ + tid + 256];

    int t0 = 2*tid, t1 = 2*tid + 1;
    float lf0 = g_lf[bh*S_ + t0], lf1 = g_lf[bh*S_ + t1];
    float ig0 = g_ig[bh*S_ + t0], ig1 = g_ig[bh*S_ + t1];

    float v = lf0 + lf1;
    #pragma unroll
    for (int o = 1; o < 32; o <<= 1) {
        float u = __shfl_up_sync(0xffffffffu, v, o);
        if (lane >= o) v += u;
    }
    if (lane == 31) wtot[wrp] = v;
    __syncthreads();
    if (tid < 8) { float t = 0.f; for (int i = 0; i < tid; i++) t += wtot[i]; woff[tid] = t; }
    __syncthreads();
    float cin  = v + woff[wrp];
    float c0   = cin - lf1;
    float total = woff[7] + wtot[7];
    float logd0 = (total - c0)  + ig0;
    float logd1 = (total - cin) + ig1;

    red[tid] = fmaxf(logd0, logd1);
    __syncthreads();
    for (int o = 128; o > 0; o >>= 1) { if (tid < o) red[tid] = fmaxf(red[tid], red[tid+o]); __syncthreads(); }
    float maxd = red[0];
    __syncthreads();

    float d0 = expf(logd0 - maxd), d1 = expf(logd1 - maxd);
    s_w[t0] = d0; s_w[t1] = d1;
    __syncthreads();

    const float* kb = g_k + bh*S_*DH_;
    for (int t = wrp; t < S_; t += 8) {
        const float* kr = kb + (size_t)t*DH_;
        float p = 0.f;
        #pragma unroll
        for (int i = 0; i < 2; i++) {
            int d = lane*4 + i*128;
            float4 kv = *(const float4*)&kr[d];
            p += s_q[d]*kv.x + s_q[d+1]*kv.y + s_q[d+2]*kv.z + s_q[d+3]*kv.w;
        }
        #pragma unroll
        for (int o = 16; o > 0; o >>= 1) p += __shfl_xor_sync(0xffffffffu, p, o);
        if (lane == 0) s_qk[t] = p * 0.0625f;
    }
    __syncthreads();

    float cm0 = s_qk[t0]*d0, cm1 = s_qk[t1]*d1;
    red[tid] = cm0 + cm1;
    __syncthreads();
    for (int o = 128; o > 0; o >>= 1) { if (tid < o) red[tid] += red[tid+o]; __syncthreads(); }
    float csum = red[0];
    __syncthreads();
    float inv = 1.f / (fmaxf(fabsf(csum), expf(-maxd)) + 1e-6f);
    s_w[t0] = cm0*inv; s_w[t1] = cm1*inv;
    __syncthreads();

    for (int j = 0; j < 32; j++) {
        int cl = wrp*32 + j;
        const float* wz = wup + (size_t)(INNER_ + h*DH_ + cl)*E_;
        float p = 0.f;
        #pragma unroll
        for (int i = 0; i < 4; i++) {
            float4 t = *(const float4*)&wz[lane*4 + i*128];
            int e = lane*4 + i*128;
            p += s_hr[e]*t.x + s_hr[e+1]*t.y + s_hr[e+2]*t.z + s_hr[e+3]*t.w;
        }
        #pragma unroll
        for (int o = 16; o > 0; o >>= 1) p += __shfl_xor_sync(0xffffffffu, p, o);
        if (lane == 0) s_z[cl] = p;
    }

    const float* vb = g_v + bh*S_*DH_;
    float acc = 0.f;
    #pragma unroll 8
    for (int t = 0; t < S_; t++) acc += s_w[t]*vb[(size_t)t*DH_ + tid];

    red[tid] = acc; __syncthreads();
    for (int o = 128; o > 0; o >>= 1) { if (tid < o) red[tid] += red[tid+o]; __syncthreads(); }
    float mu = red[0] * (1.f/DH_);
    __syncthreads();
    red[tid] = acc*acc; __syncthreads();
    for (int o = 128; o > 0; o >>= 1) { if (tid < o) red[tid] += red[tid+o]; __syncthreads(); }
    float var = red[0]*(1.f/DH_) - mu*mu;
    float hn = (acc - mu) * rsqrtf(var + 1e-5f);

    int c = h*DH_ + tid;
    float z = s_z[tid];
    float hs = (hn*onormw[c] + skipw[c]*g_xa_last[b*INNER_ + c]) * silu_f(z);
    g_hs[b*INNER_ + c] = hs;
}

// ---------------- K5: down-proj (last pos) + post-LN + head ----------------
__global__ void k5_final(const float* __restrict__ wdown, const float* __restrict__ lnpw,
                         const float* __restrict__ fcw, const float* __restrict__ fcb,
                         float* __restrict__ out)
{
    int b = blockIdx.x;
    int tid = threadIdx.x;
    int lane = tid & 31, wrp = tid >> 5;

    __shared__ float s_hs[INNER_];
    __shared__ float s_y[E_];
    __shared__ float red[512];

    s_hs[tid]       = g_hs[b*INNER_ + tid];
    s_hs[tid + 512] = g_hs[b*INNER_ + tid + 512];
    __syncthreads();

    for (int e = wrp; e < E_; e += 16) {
        const float* wr = wdown + (size_t)e*INNER_;
        float p = 0.f;
        #pragma unroll
        for (int c = lane; c < INNER_; c += 32) p += s_hs[c]*wr[c];
        #pragma unroll
        for (int o = 16; o > 0; o >>= 1) p += __shfl_xor_sync(0xffffffffu, p, o);
        if (lane == 0) s_y[e] = g_res_last[b*E_ + e] + p;
    }
    __syncthreads();

    float xv = s_y[tid];
    red[tid] = xv; __syncthreads();
    for (int o = 256; o > 0; o >>= 1) { if (tid < o) red[tid] += red[tid+o]; __syncthreads(); }
    float mean = red[0] * (1.f/E_);
    __syncthreads();
    red[tid] = xv*xv; __syncthreads();
    for (int o = 256; o > 0; o >>= 1) { if (tid < o) red[tid] += red[tid+o]; __syncthreads(); }
    float var = red[0]*(1.f/E_) - mean*mean;
    float xf = (xv - mean) * rsqrtf(var + 1e-5f) * lnpw[tid];
    __syncthreads();
    red[tid] = xf * fcw[tid]; __syncthreads();
    for (int o = 256; o > 0; o >>= 1) { if (tid < o) red[tid] += red[tid+o]; __syncthreads(); }
    if (tid == 0) out[b] = 1.f / (1.f + expf(-(red[0] + fcb[0])));
}

// ---------------- stream resources (created once, on the uncaptured correctness call) ----------------
struct PipeRes {
    cudaStream_t s2;
    cudaEvent_t evFork, evJoin;
    bool ok;
    PipeRes() {
        ok = (cudaStreamCreateWithFlags(&s2, cudaStreamNonBlocking) == cudaSuccess);
        if (!ok) s2 = 0;
        cudaEventCreateWithFlags(&evFork, cudaEventDisableTiming);
        cudaEventCreateWithFlags(&evJoin, cudaEventDisableTiming);
    }
};

// ---------------- launch: 2-way batch pipeline (fork/join) ----------------
extern "C" void kernel_launch(void* const* d_in, const int* in_sizes, int n_in,
                              void* d_out, int out_size)
{
    static PipeRes pr;   // created on first (uncaptured) call; identical work every call

    const int*   tokens = (const int*)  d_in[0];
    const float* emb    = (const float*)d_in[1];
    const float* ln1w   = (const float*)d_in[2];
    const float* convw  = (const float*)d_in[3];
    const float* convb  = (const float*)d_in[4];
    const float* wup    = (const float*)d_in[5];
    const float* qw     = (const float*)d_in[6];
    const float* kw     = (const float*)d_in[7];
    const float* vw     = (const float*)d_in[8];
    const float* igw    = (const float*)d_in[9];
    const float* igb    = (const float*)d_in[10];
    const float* fgw    = (const float*)d_in[11];
    const float* fgb    = (const float*)d_in[12];
    const float* onormw = (const float*)d_in[13];
    const float* skipw  = (const float*)d_in[14];
    const float* wdown  = (const float*)d_in[15];
    const float* lnpw   = (const float*)d_in[16];
    const float* fcw    = (const float*)d_in[17];
    const float* fcb    = (const float*)d_in[18];
    float* out = (float*)d_out;

    cudaFuncSetAttribute(k2_gemm_up, cudaFuncAttributeMaxDynamicSharedMemorySize, K2_SMEM);

    cudaStream_t s0 = 0;
    cudaStream_t s2 = pr.ok ? pr.s2 : (cudaStream_t)0;

    // shared prologue on the capture stream
    k0_round_wup<<<(INNER_*E_)/(256*4), 256, 0, s0>>>(wup);
    cudaEventRecord(pr.evFork, s0);
    if (pr.ok) cudaStreamWaitEvent(s2, pr.evFork, 0);

    // ---- half 0 (batches 0..15) on capture stream ----
    k1_embed_ln<<<M_TOK/2, 256, 0, s0>>>(tokens, emb, ln1w, 0);
    {
        dim3 g2(INNER_/TBN, (M_TOK/2)/TBM);
        k2_gemm_up<<<g2, 256, K2_SMEM, s0>>>(0);
    }
    {
        dim3 g3(S_/8, HALF_B, 2);
        k3_conv_qkv<<<g3, 256, 0, s0>>>(convw, convb, qw, kw, vw, 0);
    }
    k3b_gates<<<256, 256, 0, s0>>>(igw, igb, fgw, fgb, 0);
    k4_mlstm<<<HALF_B*NH_, 256, 0, s0>>>(wup, onormw, skipw, 0);

    // ---- half 1 (batches 16..31) on side stream ----
    k1_embed_ln<<<M_TOK/2, 256, 0, s2>>>(tokens, emb, ln1w, M_TOK/2);
    {
        dim3 g2(INNER_/TBN, (M_TOK/2)/TBM);
        k2_gemm_up<<<g2, 256, K2_SMEM, s2>>>((M_TOK/2)/TBM);
    }
    {
        dim3 g3(S_/8, HALF_B, 2);
        k3_conv_qkv<<<g3, 256, 0, s2>>>(convw, convb, qw, kw, vw, HALF_B);
    }
    k3b_gates<<<256, 256, 0, s2>>>(igw, igb, fgw, fgb, HALF_B);
    k4_mlstm<<<HALF_B*NH_, 256, 0, s2>>>(wup, onormw, skipw, HALF_B);

    // ---- join, then final reduce over all batches ----
    if (pr.ok) {
        cudaEventRecord(pr.evJoin, s2);
        cudaStreamWaitEvent(s0, pr.evJoin, 0);
    }
    k5_final<<<B_, 512, 0, s0>>>(wdown, lnpw, fcw, fcb, out);
}

// round 13
// speedup vs baseline: 1.1286x; 1.1286x over previous
#include <cuda_runtime.h>
#include <cuda_bf16.h>
#include <math.h>
#include <stddef.h>
#include <stdint.h>

#define B_   32
#define S_   512
#define E_   512
#define INNER_ 1024
#define NH_  4
#define DH_  256
#define M_TOK (B_*S_)   // 16384

// ---------------- scratch (device globals: allocation-free) ----------------
__device__ __nv_bfloat16 g_hb[(size_t)M_TOK*E_];   // LN'd embeddings, bf16 (16 MB)
__device__ __nv_bfloat16 g_wtb[(size_t)INNER_*E_]; // w_up first half, bf16 (1 MB)
__device__ float g_xm[(size_t)M_TOK*INNER_];     // up-proj first half   (64 MB)
__device__ float g_q[(size_t)B_*NH_*S_*DH_];     // q  [b][h][t][d]      (64 MB)
__device__ float g_k[(size_t)B_*NH_*S_*DH_];     // k                    (64 MB)
__device__ float g_v[(size_t)B_*NH_*S_*DH_];     // v                    (64 MB)
__device__ float g_ig[B_*NH_*S_];
__device__ float g_lf[B_*NH_*S_];                // log_sigmoid(fg)
__device__ float g_qk[B_*NH_*S_];                // q_last . k_t / 16
__device__ float g_w[B_*NH_*S_];                 // normalized mLSTM weights
__device__ float g_z[B_*INNER_];                 // z at s=511
__device__ float g_part[B_*NH_*4*DH_];           // hc partial sums
__device__ float g_hlast[B_*E_];                 // LN'd embedding at s=511 (fp32)
__device__ float g_res_last[B_*E_];
__device__ float g_xa_last[B_*INNER_];
__device__ float g_hs[B_*INNER_];

__device__ __forceinline__ float silu_f(float x) { return x / (1.f + expf(-x)); }

// MUFU-free silu: exp2-based e^x + Newton reciprocal
__device__ __forceinline__ float silu_fast(float x) {
    float t = x * 1.44269504f;
    int   ni = __float2int_rn(t);
    float r  = t - (float)ni;
    float p  = 0.0018775767f;
    p = p*r + 0.0089893397f;
    p = p*r + 0.055826318f;
    p = p*r + 0.24015361f;
    p = p*r + 0.69315308f;
    p = p*r + 1.0f;
    float ex = __int_as_float((ni + 127) << 23) * p;
    float d  = 1.f + ex;
    float rr = __int_as_float(0x7EF311C3 - __float_as_int(d));
    rr = rr*(2.f - d*rr);
    rr = rr*(2.f - d*rr);
    rr = rr*(2.f - d*rr);
    return x * ex * rr;
}

__device__ __forceinline__ void cp16(void* smem, const void* gmem) {
    uint32_t s = (uint32_t)__cvta_generic_to_shared(smem);
    asm volatile("cp.async.cg.shared.global [%0], [%1], 16;" :: "r"(s), "l"(gmem));
}

// ---------------- K0: convert w_up first half to bf16 ----------------
__global__ void k0_round_wup(const float* __restrict__ wup)
{
    int i = (blockIdx.x * 256 + threadIdx.x) * 4;
    float4 t = *(const float4*)&wup[i];
    g_wtb[i+0] = __float2bfloat16_rn(t.x);
    g_wtb[i+1] = __float2bfloat16_rn(t.y);
    g_wtb[i+2] = __float2bfloat16_rn(t.z);
    g_wtb[i+3] = __float2bfloat16_rn(t.w);
}

// ---------------- K1: embedding gather + LayerNorm (bf16 out for GEMM) ----------------
__global__ void k1_embed_ln(const int* __restrict__ tokens,
                            const float* __restrict__ emb,
                            const float* __restrict__ ln1w)
{
    int m = blockIdx.x;
    int tid = threadIdx.x;
    int tok = tokens[m];
    float x0 = 0.f, x1 = 0.f;
    if (tok != 0) {
        const float* row = emb + (size_t)tok * E_;
        x0 = row[tid];
        x1 = row[tid + 256];
    }
    __shared__ float red[256];
    red[tid] = x0 + x1;
    __syncthreads();
    for (int o = 128; o > 0; o >>= 1) { if (tid < o) red[tid] += red[tid+o]; __syncthreads(); }
    float mean = red[0] * (1.f / E_);
    __syncthreads();
    red[tid] = x0*x0 + x1*x1;
    __syncthreads();
    for (int o = 128; o > 0; o >>= 1) { if (tid < o) red[tid] += red[tid+o]; __syncthreads(); }
    float var = red[0] * (1.f / E_) - mean*mean;
    float rstd = rsqrtf(var + 1e-5f);

    float h0 = (x0 - mean) * rstd * ln1w[tid];
    float h1 = (x1 - mean) * rstd * ln1w[tid + 256];
    g_hb[(size_t)m*E_ + tid]       = __float2bfloat16_rn(h0);
    g_hb[(size_t)m*E_ + tid + 256] = __float2bfloat16_rn(h1);

    if ((m & (S_-1)) == S_-1) {
        int b = m >> 9;
        g_res_last[b*E_ + tid]       = x0;
        g_res_last[b*E_ + tid + 256] = x1;
        g_hlast[b*E_ + tid]       = h0;
        g_hlast[b*E_ + tid + 256] = h1;
    }
}

// ---------------- K4z: z-projection at s=511 (w_up second half) ----------------
// grid (B_*8) = 256 blocks; block 256 = 8 warps; warp handles 16 channels
__global__ void k4z_zproj(const float* __restrict__ wup)
{
    int blk = blockIdx.x;
    int b = blk >> 3, seg = blk & 7;        // seg: 128-channel segment
    int tid = threadIdx.x;
    int lane = tid & 31, wrp = tid >> 5;

    __shared__ float s_hr[E_];
    s_hr[tid]       = g_hlast[b*E_ + tid];
    s_hr[tid + 256] = g_hlast[b*E_ + tid + 256];
    __syncthreads();

    #pragma unroll
    for (int j = 0; j < 16; j++) {
        int c = seg*128 + wrp*16 + j;
        const float* wz = wup + (size_t)(INNER_ + c)*E_;
        float p = 0.f;
        #pragma unroll
        for (int i = 0; i < 4; i++) {
            int e = lane*4 + i*128;
            float4 t = *(const float4*)&wz[e];
            p += s_hr[e]*t.x + s_hr[e+1]*t.y + s_hr[e+2]*t.z + s_hr[e+3]*t.w;
        }
        #pragma unroll
        for (int o = 16; o > 0; o >>= 1) p += __shfl_xor_sync(0xffffffffu, p, o);
        if (lane == 0) g_z[b*INNER_ + c] = p;
    }
}

// ---------------- K2: up-projection GEMM via bf16 mma.sync + cp.async ----------------
#define TBM 128
#define TBN 128
#define NIT 16
#define STAGES 3
#define APITCH 20
#define TILE_U32 (TBM*APITCH)
#define K2_SMEM (STAGES*2*TILE_U32*4)

__global__ void __launch_bounds__(256) k2_gemm_up()
{
    extern __shared__ uint32_t sm[];
    uint32_t* As = sm;
    uint32_t* Bs = sm + STAGES*TILE_U32;

    int tid  = threadIdx.x;
    int lane = tid & 31;
    int wid  = tid >> 5;
    int warp_m = wid & 1;
    int warp_n = wid >> 1;
    int g  = lane >> 2;
    int tg = lane & 3;

    int m0 = blockIdx.y * TBM;
    int n0 = blockIdx.x * TBN;

    float c[4][4][4];
    #pragma unroll
    for (int mt = 0; mt < 4; mt++)
        #pragma unroll
        for (int nt = 0; nt < 4; nt++)
            #pragma unroll
            for (int r = 0; r < 4; r++) c[mt][nt][r] = 0.f;

    #pragma unroll
    for (int p = 0; p < STAGES-1; p++) {
        #pragma unroll
        for (int j = 0; j < 2; j++) {
            int u = tid + j*256;
            int r = u >> 2, q = u & 3;
            cp16(&As[p*TILE_U32 + r*APITCH + q*4], &g_hb[(size_t)(m0+r)*E_ + p*32 + q*8]);
            cp16(&Bs[p*TILE_U32 + r*APITCH + q*4], &g_wtb[(size_t)(n0+r)*E_ + p*32 + q*8]);
        }
        asm volatile("cp.async.commit_group;");
    }

    for (int it = 0; it < NIT; it++) {
        int pf = it + STAGES - 1;
        if (pf < NIT) {
            int st = pf % STAGES;
            #pragma unroll
            for (int j = 0; j < 2; j++) {
                int u = tid + j*256;
                int r = u >> 2, q = u & 3;
                cp16(&As[st*TILE_U32 + r*APITCH + q*4], &g_hb[(size_t)(m0+r)*E_ + pf*32 + q*8]);
                cp16(&Bs[st*TILE_U32 + r*APITCH + q*4], &g_wtb[(size_t)(n0+r)*E_ + pf*32 + q*8]);
            }
        }
        asm volatile("cp.async.commit_group;");
        asm volatile("cp.async.wait_group %0;" :: "n"(STAGES-1));
        __syncthreads();

        const uint32_t* Ab = &As[(it % STAGES)*TILE_U32];
        const uint32_t* Bb = &Bs[(it % STAGES)*TILE_U32];
        #pragma unroll
        for (int ks = 0; ks < 2; ks++) {
            int kb = ks * 8;
            uint32_t af[4][4], bf[4][2];
            #pragma unroll
            for (int mt = 0; mt < 4; mt++) {
                int row = warp_m*64 + mt*16 + g;
                af[mt][0] = Ab[row*APITCH + kb+tg];
                af[mt][1] = Ab[(row+8)*APITCH + kb+tg];
                af[mt][2] = Ab[row*APITCH + kb+tg+4];
                af[mt][3] = Ab[(row+8)*APITCH + kb+tg+4];
            }
            #pragma unroll
            for (int nt = 0; nt < 4; nt++) {
                int n = warp_n*32 + nt*8 + g;
                bf[nt][0] = Bb[n*APITCH + kb+tg];
                bf[nt][1] = Bb[n*APITCH + kb+tg+4];
            }
            #pragma unroll
            for (int mt = 0; mt < 4; mt++)
                #pragma unroll
                for (int nt = 0; nt < 4; nt++) {
                    asm volatile(
                        "mma.sync.aligned.m16n8k16.row.col.f32.bf16.bf16.f32 "
                        "{%0,%1,%2,%3}, {%4,%5,%6,%7}, {%8,%9}, {%0,%1,%2,%3};"
                        : "+f"(c[mt][nt][0]), "+f"(c[mt][nt][1]),
                          "+f"(c[mt][nt][2]), "+f"(c[mt][nt][3])
                        : "r"(af[mt][0]), "r"(af[mt][1]), "r"(af[mt][2]), "r"(af[mt][3]),
                          "r"(bf[nt][0]), "r"(bf[nt][1]));
                }
        }
        __syncthreads();
    }

    #pragma unroll
    for (int mt = 0; mt < 4; mt++) {
        int row = m0 + warp_m*64 + mt*16 + g;
        #pragma unroll
        for (int nt = 0; nt < 4; nt++) {
            int col = n0 + warp_n*32 + nt*8 + 2*tg;
            *(float2*)&g_xm[(size_t)row*INNER_ + col]     = make_float2(c[mt][nt][0], c[mt][nt][1]);
            *(float2*)&g_xm[(size_t)(row+8)*INNER_ + col] = make_float2(c[mt][nt][2], c[mt][nt][3]);
        }
    }
}

// ---------------- K3: causal conv + silu + block-diag q/k/v ----------------
__global__ void __launch_bounds__(256) k3_conv_qkv(
        const float* __restrict__ convw, const float* __restrict__ convb,
        const float* __restrict__ qw, const float* __restrict__ kw,
        const float* __restrict__ vw)
{
    int t  = threadIdx.x;
    int b  = blockIdx.y;
    int s0 = blockIdx.x * 8;
    int c0 = blockIdx.z * 512 + 2*t;
    int qd = c0 >> 2;
    int hf = (c0 >> 1) & 1;

    float cw[2][4], cb2[2], qwr[2][4], kwr[2][4], vwr[2][4];
    #pragma unroll
    for (int o = 0; o < 2; o++) {
        int ch = c0 + o;
        int oq = hf*2 + o;
        cb2[o] = convb[ch];
        #pragma unroll
        for (int j = 0; j < 4; j++) cw[o][j] = convw[ch*4 + j];
        #pragma unroll
        for (int i = 0; i < 4; i++) {
            qwr[o][i] = qw[qd*16 + oq*4 + i];
            kwr[o][i] = kw[qd*16 + oq*4 + i];
            vwr[o][i] = vw[qd*16 + oq*4 + i];
        }
    }

    float win[4][2];
    #pragma unroll
    for (int j = 0; j < 3; j++) {
        int s = s0 - 3 + j;
        if (s >= 0) {
            float2 xm = *(const float2*)&g_xm[((size_t)b*S_ + s)*INNER_ + c0];
            win[j][0] = xm.x; win[j][1] = xm.y;
        } else { win[j][0] = 0.f; win[j][1] = 0.f; }
    }

    int h  = c0 >> 8;
    int dd = c0 & 255;

    for (int ss = 0; ss < 8; ss++) {
        int s = s0 + ss;
        float2 xm = *(const float2*)&g_xm[((size_t)b*S_ + s)*INNER_ + c0];
        win[3][0] = xm.x; win[3][1] = xm.y;

        float xa0, xa1;
        {
            float a0 = cb2[0], a1 = cb2[1];
            #pragma unroll
            for (int j = 0; j < 4; j++) { a0 += win[j][0]*cw[0][j]; a1 += win[j][1]*cw[1][j]; }
            xa0 = silu_fast(a0); xa1 = silu_fast(a1);
        }
        float pxa0 = __shfl_xor_sync(0xffffffffu, xa0, 1);
        float pxa1 = __shfl_xor_sync(0xffffffffu, xa1, 1);
        float pxm0 = __shfl_xor_sync(0xffffffffu, xm.x, 1);
        float pxm1 = __shfl_xor_sync(0xffffffffu, xm.y, 1);

        float xaq[4], xmq[4];
        if (hf == 0) {
            xaq[0]=xa0;  xaq[1]=xa1;  xaq[2]=pxa0; xaq[3]=pxa1;
            xmq[0]=xm.x; xmq[1]=xm.y; xmq[2]=pxm0; xmq[3]=pxm1;
        } else {
            xaq[0]=pxa0; xaq[1]=pxa1; xaq[2]=xa0;  xaq[3]=xa1;
            xmq[0]=pxm0; xmq[1]=pxm1; xmq[2]=xm.x; xmq[3]=xm.y;
        }

        float qv[2], kv[2], vv[2];
        #pragma unroll
        for (int o = 0; o < 2; o++) {
            float a = 0.f, bk = 0.f, c2 = 0.f;
            #pragma unroll
            for (int i = 0; i < 4; i++) {
                a  += xaq[i]*qwr[o][i];
                bk += xaq[i]*kwr[o][i];
                c2 += xmq[i]*vwr[o][i];
            }
            qv[o] = a; kv[o] = bk; vv[o] = c2;
        }
        size_t base = (((size_t)b*NH_ + h)*S_ + s)*DH_ + dd;
        *(float2*)&g_q[base] = make_float2(qv[0], qv[1]);
        *(float2*)&g_k[base] = make_float2(kv[0], kv[1]);
        *(float2*)&g_v[base] = make_float2(vv[0], vv[1]);
        if (s == S_-1)
            *(float2*)&g_xa_last[b*INNER_ + c0] = make_float2(xa0, xa1);

        #pragma unroll
        for (int o = 0; o < 2; o++) { win[0][o]=win[1][o]; win[1][o]=win[2][o]; win[2][o]=win[3][o]; }
    }
}

// ---------------- K3b: ig/fg gates, float4-vectorized ----------------
__global__ void k3b_gates(const float* __restrict__ igw, const float* __restrict__ igb,
                          const float* __restrict__ fgw, const float* __restrict__ fgb)
{
    int tid = threadIdx.x;
    int lane = tid & 31, w = tid >> 5;
    int blk = blockIdx.x;
    int b = blk >> 4;
    int t0 = (blk & 15) * 32 + w * 4;

    float aI[4][4], aF[4][4];
    #pragma unroll
    for (int r = 0; r < 4; r++)
        #pragma unroll
        for (int g = 0; g < 4; g++) { aI[r][g] = 0.f; aF[r][g] = 0.f; }

    const float* segp[3] = { g_q, g_k, g_v };
    #pragma unroll
    for (int seg = 0; seg < 3; seg++) {
        const float* P = segp[seg];
        #pragma unroll
        for (int c0 = 0; c0 < INNER_; c0 += 128) {
            int cw_ = c0 + lane*4;
            int hh = cw_ >> 8, dd = cw_ & 255;
            float4 wI4[4], wF4[4];
            #pragma unroll
            for (int g = 0; g < 4; g++) {
                wI4[g] = *(const float4*)&igw[g*3072 + seg*1024 + cw_];
                wF4[g] = *(const float4*)&fgw[g*3072 + seg*1024 + cw_];
            }
            size_t rb = (((size_t)b*NH_ + hh)*S_ + t0)*DH_ + dd;
            #pragma unroll
            for (int r = 0; r < 4; r++) {
                float4 val = *(const float4*)&P[rb + (size_t)r*DH_];
                #pragma unroll
                for (int g = 0; g < 4; g++) {
                    aI[r][g] += val.x*wI4[g].x + val.y*wI4[g].y + val.z*wI4[g].z + val.w*wI4[g].w;
                    aF[r][g] += val.x*wF4[g].x + val.y*wF4[g].y + val.z*wF4[g].z + val.w*wF4[g].w;
                }
            }
        }
    }
    #pragma unroll
    for (int r = 0; r < 4; r++) {
        #pragma unroll
        for (int g = 0; g < 4; g++) {
            float sI = aI[r][g], sF = aF[r][g];
            #pragma unroll
            for (int o = 16; o > 0; o >>= 1) {
                sI += __shfl_xor_sync(0xffffffffu, sI, o);
                sF += __shfl_xor_sync(0xffffffffu, sF, o);
            }
            if (lane == 0) {
                int t = t0 + r;
                g_ig[(b*NH_+g)*S_ + t] = sI + igb[g];
                float fgv = sF + fgb[g];
                float lf = (fgv >= 0.f) ? -log1pf(expf(-fgv)) : (fgv - log1pf(expf(fgv)));
                g_lf[(b*NH_+g)*S_ + t] = lf;
            }
        }
    }
}

// ---------------- K4a: qk dots, 4 t-chunks per bh (512 blocks) ----------------
__global__ void k4a_qk()
{
    int bh = blockIdx.x;
    int chunk = blockIdx.y;
    int tid = threadIdx.x;
    int lane = tid & 31, wrp = tid >> 5;

    __shared__ float s_q[DH_];
    s_q[tid] = g_q[((size_t)bh*S_ + (S_-1))*DH_ + tid];
    __syncthreads();

    const float* kb = g_k + (size_t)bh*S_*DH_;
    for (int t = wrp; t < 128; t += 8) {
        int tt = chunk*128 + t;
        const float* kr = kb + (size_t)tt*DH_;
        float p = 0.f;
        #pragma unroll
        for (int i = 0; i < 2; i++) {
            int d = lane*4 + i*128;
            float4 kv = *(const float4*)&kr[d];
            p += s_q[d]*kv.x + s_q[d+1]*kv.y + s_q[d+2]*kv.z + s_q[d+3]*kv.w;
        }
        #pragma unroll
        for (int o = 16; o > 0; o >>= 1) p += __shfl_xor_sync(0xffffffffu, p, o);
        if (lane == 0) g_qk[bh*S_ + tt] = p * 0.0625f;
    }
}

// ---------------- K4w: scan/max/normalize -> weights (128 blocks) ----------------
__global__ void k4w_weights()
{
    int bh = blockIdx.x;
    int tid = threadIdx.x;
    int lane = tid & 31, wrp = tid >> 5;

    __shared__ float red[256];
    __shared__ float wtot[8], woff[8];

    int t0 = 2*tid, t1 = 2*tid + 1;
    float lf0 = g_lf[bh*S_ + t0], lf1 = g_lf[bh*S_ + t1];
    float ig0 = g_ig[bh*S_ + t0], ig1 = g_ig[bh*S_ + t1];

    float v = lf0 + lf1;
    #pragma unroll
    for (int o = 1; o < 32; o <<= 1) {
        float u = __shfl_up_sync(0xffffffffu, v, o);
        if (lane >= o) v += u;
    }
    if (lane == 31) wtot[wrp] = v;
    __syncthreads();
    if (tid < 8) { float t = 0.f; for (int i = 0; i < tid; i++) t += wtot[i]; woff[tid] = t; }
    __syncthreads();
    float cin  = v + woff[wrp];
    float c0   = cin - lf1;
    float total = woff[7] + wtot[7];
    float logd0 = (total - c0)  + ig0;
    float logd1 = (total - cin) + ig1;

    red[tid] = fmaxf(logd0, logd1);
    __syncthreads();
    for (int o = 128; o > 0; o >>= 1) { if (tid < o) red[tid] = fmaxf(red[tid], red[tid+o]); __syncthreads(); }
    float maxd = red[0];
    __syncthreads();

    float d0 = expf(logd0 - maxd), d1 = expf(logd1 - maxd);
    float cm0 = g_qk[bh*S_ + t0]*d0, cm1 = g_qk[bh*S_ + t1]*d1;
    red[tid] = cm0 + cm1;
    __syncthreads();
    for (int o = 128; o > 0; o >>= 1) { if (tid < o) red[tid] += red[tid+o]; __syncthreads(); }
    float csum = red[0];
    float inv = 1.f / (fmaxf(fabsf(csum), expf(-maxd)) + 1e-6f);
    g_w[bh*S_ + t0] = cm0*inv;
    g_w[bh*S_ + t1] = cm1*inv;
}

// ---------------- K4b: hc partial sums over 4 t-chunks (512 blocks) ----------------
__global__ void k4b_hcpart()
{
    int bh = blockIdx.x;
    int chunk = blockIdx.y;
    int tid = threadIdx.x;

    __shared__ float s_w[128];
    if (tid < 128) s_w[tid] = g_w[bh*S_ + chunk*128 + tid];
    __syncthreads();

    const float* vb = g_v + ((size_t)bh*S_ + chunk*128)*DH_;
    float acc = 0.f;
    #pragma unroll 8
    for (int t = 0; t < 128; t++) acc += s_w[t]*vb[(size_t)t*DH_ + tid];
    g_part[(bh*4 + chunk)*DH_ + tid] = acc;
}

// ---------------- K4c: combine partials + head-LN + hs (128 blocks) ----------------
__global__ void k4c_final(const float* __restrict__ onormw, const float* __restrict__ skipw)
{
    int bh = blockIdx.x;
    int b = bh >> 2, h = bh & 3;
    int tid = threadIdx.x;

    __shared__ float red[256];

    float acc = g_part[(bh*4+0)*DH_ + tid] + g_part[(bh*4+1)*DH_ + tid]
              + g_part[(bh*4+2)*DH_ + tid] + g_part[(bh*4+3)*DH_ + tid];

    red[tid] = acc; __syncthreads();
    for (int o = 128; o > 0; o >>= 1) { if (tid < o) red[tid] += red[tid+o]; __syncthreads(); }
    float mu = red[0] * (1.f/DH_);
    __syncthreads();
    red[tid] = acc*acc; __syncthreads();
    for (int o = 128; o > 0; o >>= 1) { if (tid < o) red[tid] += red[tid+o]; __syncthreads(); }
    float var = red[0]*(1.f/DH_) - mu*mu;
    float hn = (acc - mu) * rsqrtf(var + 1e-5f);

    int c = h*DH_ + tid;
    float z = g_z[b*INNER_ + c];
    float hs = (hn*onormw[c] + skipw[c]*g_xa_last[b*INNER_ + c]) * silu_f(z);
    g_hs[b*INNER_ + c] = hs;
}

// ---------------- K5: down-proj (last pos) + post-LN + head ----------------
__global__ void k5_final(const float* __restrict__ wdown, const float* __restrict__ lnpw,
                         const float* __restrict__ fcw, const float* __restrict__ fcb,
                         float* __restrict__ out)
{
    int b = blockIdx.x;
    int tid = threadIdx.x;
    int lane = tid & 31, wrp = tid >> 5;

    __shared__ float s_hs[INNER_];
    __shared__ float s_y[E_];
    __shared__ float red[512];

    s_hs[tid]       = g_hs[b*INNER_ + tid];
    s_hs[tid + 512] = g_hs[b*INNER_ + tid + 512];
    __syncthreads();

    for (int e = wrp; e < E_; e += 16) {
        const float* wr = wdown + (size_t)e*INNER_;
        float p = 0.f;
        #pragma unroll
        for (int c = lane; c < INNER_; c += 32) p += s_hs[c]*wr[c];
        #pragma unroll
        for (int o = 16; o > 0; o >>= 1) p += __shfl_xor_sync(0xffffffffu, p, o);
        if (lane == 0) s_y[e] = g_res_last[b*E_ + e] + p;
    }
    __syncthreads();

    float xv = s_y[tid];
    red[tid] = xv; __syncthreads();
    for (int o = 256; o > 0; o >>= 1) { if (tid < o) red[tid] += red[tid+o]; __syncthreads(); }
    float mean = red[0] * (1.f/E_);
    __syncthreads();
    red[tid] = xv*xv; __syncthreads();
    for (int o = 256; o > 0; o >>= 1) { if (tid < o) red[tid] += red[tid+o]; __syncthreads(); }
    float var = red[0]*(1.f/E_) - mean*mean;
    float xf = (xv - mean) * rsqrtf(var + 1e-5f) * lnpw[tid];
    __syncthreads();
    red[tid] = xf * fcw[tid]; __syncthreads();
    for (int o = 256; o > 0; o >>= 1) { if (tid < o) red[tid] += red[tid+o]; __syncthreads(); }
    if (tid == 0) out[b] = 1.f / (1.f + expf(-(red[0] + fcb[0])));
}

// ---------------- launch ----------------
extern "C" void kernel_launch(void* const* d_in, const int* in_sizes, int n_in,
                              void* d_out, int out_size)
{
    const int*   tokens = (const int*)  d_in[0];
    const float* emb    = (const float*)d_in[1];
    const float* ln1w   = (const float*)d_in[2];
    const float* convw  = (const float*)d_in[3];
    const float* convb  = (const float*)d_in[4];
    const float* wup    = (const float*)d_in[5];
    const float* qw     = (const float*)d_in[6];
    const float* kw     = (const float*)d_in[7];
    const float* vw     = (const float*)d_in[8];
    const float* igw    = (const float*)d_in[9];
    const float* igb    = (const float*)d_in[10];
    const float* fgw    = (const float*)d_in[11];
    const float* fgb    = (const float*)d_in[12];
    const float* onormw = (const float*)d_in[13];
    const float* skipw  = (const float*)d_in[14];
    const float* wdown  = (const float*)d_in[15];
    const float* lnpw   = (const float*)d_in[16];
    const float* fcw    = (const float*)d_in[17];
    const float* fcb    = (const float*)d_in[18];
    float* out = (float*)d_out;

    cudaFuncSetAttribute(k2_gemm_up, cudaFuncAttributeMaxDynamicSharedMemorySize, K2_SMEM);

    k0_round_wup<<<(INNER_*E_)/(256*4), 256>>>(wup);
    k1_embed_ln<<<M_TOK, 256>>>(tokens, emb, ln1w);
    k4z_zproj<<<B_*8, 256>>>(wup);
    dim3 g2(INNER_/TBN, M_TOK/TBM);
    k2_gemm_up<<<g2, 256, K2_SMEM>>>();
    dim3 g3(S_/8, B_, 2);
    k3_conv_qkv<<<g3, 256>>>(convw, convb, qw, kw, vw);
    k3b_gates<<<512, 256>>>(igw, igb, fgw, fgb);
    dim3 g4a(B_*NH_, 4);
    k4a_qk<<<g4a, 256>>>();
    k4w_weights<<<B_*NH_, 256>>>();
    dim3 g4b(B_*NH_, 4);
    k4b_hcpart<<<g4b, 256>>>();
    k4c_final<<<B_*NH_, 256>>>(onormw, skipw);
    k5_final<<<B_, 512>>>(wdown, lnpw, fcw, fcb, out);
}

// round 14
// speedup vs baseline: 1.1516x; 1.0204x over previous
#include <cuda_runtime.h>
#include <cuda_bf16.h>
#include <math.h>
#include <stddef.h>
#include <stdint.h>

#define B_   32
#define S_   512
#define E_   512
#define INNER_ 1024
#define NH_  4
#define DH_  256
#define M_TOK (B_*S_)   // 16384

// ---------------- scratch (device globals: allocation-free) ----------------
__device__ __nv_bfloat16 g_hb[(size_t)M_TOK*E_];   // LN'd embeddings, bf16 (16 MB)
__device__ __nv_bfloat16 g_wtb[(size_t)INNER_*E_]; // w_up first half, bf16 (1 MB)
__device__ float g_xm[(size_t)M_TOK*INNER_];     // up-proj first half   (64 MB)
__device__ float g_q[(size_t)B_*NH_*S_*DH_];     // q  [b][h][t][d]      (64 MB)
__device__ float g_k[(size_t)B_*NH_*S_*DH_];     // k                    (64 MB)
__device__ float g_v[(size_t)B_*NH_*S_*DH_];     // v                    (64 MB)
__device__ float g_ig[B_*NH_*S_];
__device__ float g_lf[B_*NH_*S_];                // log_sigmoid(fg)
__device__ float g_qk[B_*NH_*S_];                // q_last . k_t / 16
__device__ float g_w[B_*NH_*S_];                 // normalized mLSTM weights
__device__ float g_z[B_*INNER_];                 // z at s=511
__device__ float g_part[B_*NH_*4*DH_];           // hc partial sums
__device__ float g_hlast[B_*E_];                 // LN'd embedding at s=511 (fp32)
__device__ float g_res_last[B_*E_];
__device__ float g_xa_last[B_*INNER_];
__device__ float g_hs[B_*INNER_];

__device__ __forceinline__ float silu_f(float x) { return x / (1.f + expf(-x)); }

// MUFU-free silu: exp2-based e^x + Newton reciprocal
__device__ __forceinline__ float silu_fast(float x) {
    float t = x * 1.44269504f;
    int   ni = __float2int_rn(t);
    float r  = t - (float)ni;
    float p  = 0.0018775767f;
    p = p*r + 0.0089893397f;
    p = p*r + 0.055826318f;
    p = p*r + 0.24015361f;
    p = p*r + 0.69315308f;
    p = p*r + 1.0f;
    float ex = __int_as_float((ni + 127) << 23) * p;
    float d  = 1.f + ex;
    float rr = __int_as_float(0x7EF311C3 - __float_as_int(d));
    rr = rr*(2.f - d*rr);
    rr = rr*(2.f - d*rr);
    rr = rr*(2.f - d*rr);
    return x * ex * rr;
}

__device__ __forceinline__ void cp16(void* smem, const void* gmem) {
    uint32_t s = (uint32_t)__cvta_generic_to_shared(smem);
    asm volatile("cp.async.cg.shared.global [%0], [%1], 16;" :: "r"(s), "l"(gmem));
}

__device__ __forceinline__ void ldm_x4(uint32_t& r0, uint32_t& r1, uint32_t& r2, uint32_t& r3,
                                       uint32_t addr) {
    asm volatile("ldmatrix.sync.aligned.m8n8.x4.shared.b16 {%0,%1,%2,%3}, [%4];"
                 : "=r"(r0), "=r"(r1), "=r"(r2), "=r"(r3) : "r"(addr));
}

// ---------------- K0: convert w_up first half to bf16 ----------------
__global__ void k0_round_wup(const float* __restrict__ wup)
{
    int i = (blockIdx.x * 256 + threadIdx.x) * 4;
    float4 t = *(const float4*)&wup[i];
    g_wtb[i+0] = __float2bfloat16_rn(t.x);
    g_wtb[i+1] = __float2bfloat16_rn(t.y);
    g_wtb[i+2] = __float2bfloat16_rn(t.z);
    g_wtb[i+3] = __float2bfloat16_rn(t.w);
}

// ---------------- K1: embedding gather + LayerNorm (bf16 out for GEMM) ----------------
__global__ void k1_embed_ln(const int* __restrict__ tokens,
                            const float* __restrict__ emb,
                            const float* __restrict__ ln1w)
{
    int m = blockIdx.x;
    int tid = threadIdx.x;
    int tok = tokens[m];
    float x0 = 0.f, x1 = 0.f;
    if (tok != 0) {
        const float* row = emb + (size_t)tok * E_;
        x0 = row[tid];
        x1 = row[tid + 256];
    }
    __shared__ float red[256];
    red[tid] = x0 + x1;
    __syncthreads();
    for (int o = 128; o > 0; o >>= 1) { if (tid < o) red[tid] += red[tid+o]; __syncthreads(); }
    float mean = red[0] * (1.f / E_);
    __syncthreads();
    red[tid] = x0*x0 + x1*x1;
    __syncthreads();
    for (int o = 128; o > 0; o >>= 1) { if (tid < o) red[tid] += red[tid+o]; __syncthreads(); }
    float var = red[0] * (1.f / E_) - mean*mean;
    float rstd = rsqrtf(var + 1e-5f);

    float h0 = (x0 - mean) * rstd * ln1w[tid];
    float h1 = (x1 - mean) * rstd * ln1w[tid + 256];
    g_hb[(size_t)m*E_ + tid]       = __float2bfloat16_rn(h0);
    g_hb[(size_t)m*E_ + tid + 256] = __float2bfloat16_rn(h1);

    if ((m & (S_-1)) == S_-1) {
        int b = m >> 9;
        g_res_last[b*E_ + tid]       = x0;
        g_res_last[b*E_ + tid + 256] = x1;
        g_hlast[b*E_ + tid]       = h0;
        g_hlast[b*E_ + tid + 256] = h1;
    }
}

// ---------------- K4z: z-projection at s=511 (w_up second half) ----------------
__global__ void k4z_zproj(const float* __restrict__ wup)
{
    int blk = blockIdx.x;
    int b = blk >> 3, seg = blk & 7;
    int tid = threadIdx.x;
    int lane = tid & 31, wrp = tid >> 5;

    __shared__ float s_hr[E_];
    s_hr[tid]       = g_hlast[b*E_ + tid];
    s_hr[tid + 256] = g_hlast[b*E_ + tid + 256];
    __syncthreads();

    #pragma unroll
    for (int j = 0; j < 16; j++) {
        int c = seg*128 + wrp*16 + j;
        const float* wz = wup + (size_t)(INNER_ + c)*E_;
        float p = 0.f;
        #pragma unroll
        for (int i = 0; i < 4; i++) {
            int e = lane*4 + i*128;
            float4 t = *(const float4*)&wz[e];
            p += s_hr[e]*t.x + s_hr[e+1]*t.y + s_hr[e+2]*t.z + s_hr[e+3]*t.w;
        }
        #pragma unroll
        for (int o = 16; o > 0; o >>= 1) p += __shfl_xor_sync(0xffffffffu, p, o);
        if (lane == 0) g_z[b*INNER_ + c] = p;
    }
}

// ---------------- K2: up-projection GEMM via bf16 mma.sync + cp.async + ldmatrix ----------------
#define TBM 128
#define TBN 128
#define NIT 16
#define STAGES 3
#define APITCH 20
#define TILE_U32 (TBM*APITCH)
#define K2_SMEM (STAGES*2*TILE_U32*4)

__global__ void __launch_bounds__(256) k2_gemm_up()
{
    extern __shared__ uint32_t sm[];
    uint32_t* As = sm;
    uint32_t* Bs = sm + STAGES*TILE_U32;
    uint32_t smA_u = (uint32_t)__cvta_generic_to_shared(As);
    uint32_t smB_u = (uint32_t)__cvta_generic_to_shared(Bs);

    int tid  = threadIdx.x;
    int lane = tid & 31;
    int wid  = tid >> 5;
    int warp_m = wid & 1;
    int warp_n = wid >> 1;
    int g  = lane >> 2;
    int tg = lane & 3;

    int m0 = blockIdx.y * TBM;
    int n0 = blockIdx.x * TBN;

    // ldmatrix per-lane row selectors
    int mrow = lane & 7, midx = lane >> 3;
    // A: m0..3 -> (rows-lo k-lo, rows-hi k-lo, rows-lo k-hi, rows-hi k-hi) = a0..a3
    int a_row_add = (midx & 1) * 8;
    int a_k_add   = (midx >> 1) * 4;        // u32
    // B: m0..3 -> (n-lo k-lo, n-lo k-hi, n-hi k-lo, n-hi k-hi) = b0/b1 of two nt tiles
    int b_row_add = (midx >> 1) * 8;
    int b_k_add   = (midx & 1) * 4;         // u32

    float c[4][4][4];
    #pragma unroll
    for (int mt = 0; mt < 4; mt++)
        #pragma unroll
        for (int nt = 0; nt < 4; nt++)
            #pragma unroll
            for (int r = 0; r < 4; r++) c[mt][nt][r] = 0.f;

    #pragma unroll
    for (int p = 0; p < STAGES-1; p++) {
        #pragma unroll
        for (int j = 0; j < 2; j++) {
            int u = tid + j*256;
            int r = u >> 2, q = u & 3;
            cp16(&As[p*TILE_U32 + r*APITCH + q*4], &g_hb[(size_t)(m0+r)*E_ + p*32 + q*8]);
            cp16(&Bs[p*TILE_U32 + r*APITCH + q*4], &g_wtb[(size_t)(n0+r)*E_ + p*32 + q*8]);
        }
        asm volatile("cp.async.commit_group;");
    }

    for (int it = 0; it < NIT; it++) {
        int pf = it + STAGES - 1;
        if (pf < NIT) {
            int st = pf % STAGES;
            #pragma unroll
            for (int j = 0; j < 2; j++) {
                int u = tid + j*256;
                int r = u >> 2, q = u & 3;
                cp16(&As[st*TILE_U32 + r*APITCH + q*4], &g_hb[(size_t)(m0+r)*E_ + pf*32 + q*8]);
                cp16(&Bs[st*TILE_U32 + r*APITCH + q*4], &g_wtb[(size_t)(n0+r)*E_ + pf*32 + q*8]);
            }
        }
        asm volatile("cp.async.commit_group;");
        asm volatile("cp.async.wait_group %0;" :: "n"(STAGES-1));
        __syncthreads();

        uint32_t Ab_u = smA_u + (uint32_t)((it % STAGES)*TILE_U32)*4u;
        uint32_t Bb_u = smB_u + (uint32_t)((it % STAGES)*TILE_U32)*4u;
        #pragma unroll
        for (int ks = 0; ks < 2; ks++) {
            int kb = ks * 8;
            uint32_t af[4][4], bf[4][2];
            #pragma unroll
            for (int mt = 0; mt < 4; mt++) {
                int R = warp_m*64 + mt*16;
                uint32_t addr = Ab_u + (uint32_t)(((R + mrow + a_row_add)*APITCH) + kb + a_k_add)*4u;
                ldm_x4(af[mt][0], af[mt][1], af[mt][2], af[mt][3], addr);
            }
            #pragma unroll
            for (int bp = 0; bp < 2; bp++) {
                int nb = warp_n*32 + bp*16;
                uint32_t addr = Bb_u + (uint32_t)(((nb + mrow + b_row_add)*APITCH) + kb + b_k_add)*4u;
                ldm_x4(bf[2*bp][0], bf[2*bp][1], bf[2*bp+1][0], bf[2*bp+1][1], addr);
            }
            #pragma unroll
            for (int mt = 0; mt < 4; mt++)
                #pragma unroll
                for (int nt = 0; nt < 4; nt++) {
                    asm volatile(
                        "mma.sync.aligned.m16n8k16.row.col.f32.bf16.bf16.f32 "
                        "{%0,%1,%2,%3}, {%4,%5,%6,%7}, {%8,%9}, {%0,%1,%2,%3};"
                        : "+f"(c[mt][nt][0]), "+f"(c[mt][nt][1]),
                          "+f"(c[mt][nt][2]), "+f"(c[mt][nt][3])
                        : "r"(af[mt][0]), "r"(af[mt][1]), "r"(af[mt][2]), "r"(af[mt][3]),
                          "r"(bf[nt][0]), "r"(bf[nt][1]));
                }
        }
        __syncthreads();
    }

    #pragma unroll
    for (int mt = 0; mt < 4; mt++) {
        int row = m0 + warp_m*64 + mt*16 + g;
        #pragma unroll
        for (int nt = 0; nt < 4; nt++) {
            int col = n0 + warp_n*32 + nt*8 + 2*tg;
            *(float2*)&g_xm[(size_t)row*INNER_ + col]     = make_float2(c[mt][nt][0], c[mt][nt][1]);
            *(float2*)&g_xm[(size_t)(row+8)*INNER_ + col] = make_float2(c[mt][nt][2], c[mt][nt][3]);
        }
    }
}

// ---------------- K3: causal conv + silu + block-diag q/k/v ----------------
__global__ void __launch_bounds__(256) k3_conv_qkv(
        const float* __restrict__ convw, const float* __restrict__ convb,
        const float* __restrict__ qw, const float* __restrict__ kw,
        const float* __restrict__ vw)
{
    int t  = threadIdx.x;
    int b  = blockIdx.y;
    int s0 = blockIdx.x * 8;
    int c0 = blockIdx.z * 512 + 2*t;
    int qd = c0 >> 2;
    int hf = (c0 >> 1) & 1;

    float cw[2][4], cb2[2], qwr[2][4], kwr[2][4], vwr[2][4];
    #pragma unroll
    for (int o = 0; o < 2; o++) {
        int ch = c0 + o;
        int oq = hf*2 + o;
        cb2[o] = convb[ch];
        #pragma unroll
        for (int j = 0; j < 4; j++) cw[o][j] = convw[ch*4 + j];
        #pragma unroll
        for (int i = 0; i < 4; i++) {
            qwr[o][i] = qw[qd*16 + oq*4 + i];
            kwr[o][i] = kw[qd*16 + oq*4 + i];
            vwr[o][i] = vw[qd*16 + oq*4 + i];
        }
    }

    float win[4][2];
    #pragma unroll
    for (int j = 0; j < 3; j++) {
        int s = s0 - 3 + j;
        if (s >= 0) {
            float2 xm = *(const float2*)&g_xm[((size_t)b*S_ + s)*INNER_ + c0];
            win[j][0] = xm.x; win[j][1] = xm.y;
        } else { win[j][0] = 0.f; win[j][1] = 0.f; }
    }

    int h  = c0 >> 8;
    int dd = c0 & 255;

    for (int ss = 0; ss < 8; ss++) {
        int s = s0 + ss;
        float2 xm = *(const float2*)&g_xm[((size_t)b*S_ + s)*INNER_ + c0];
        win[3][0] = xm.x; win[3][1] = xm.y;

        float xa0, xa1;
        {
            float a0 = cb2[0], a1 = cb2[1];
            #pragma unroll
            for (int j = 0; j < 4; j++) { a0 += win[j][0]*cw[0][j]; a1 += win[j][1]*cw[1][j]; }
            xa0 = silu_fast(a0); xa1 = silu_fast(a1);
        }
        float pxa0 = __shfl_xor_sync(0xffffffffu, xa0, 1);
        float pxa1 = __shfl_xor_sync(0xffffffffu, xa1, 1);
        float pxm0 = __shfl_xor_sync(0xffffffffu, xm.x, 1);
        float pxm1 = __shfl_xor_sync(0xffffffffu, xm.y, 1);

        float xaq[4], xmq[4];
        if (hf == 0) {
            xaq[0]=xa0;  xaq[1]=xa1;  xaq[2]=pxa0; xaq[3]=pxa1;
            xmq[0]=xm.x; xmq[1]=xm.y; xmq[2]=pxm0; xmq[3]=pxm1;
        } else {
            xaq[0]=pxa0; xaq[1]=pxa1; xaq[2]=xa0;  xaq[3]=xa1;
            xmq[0]=pxm0; xmq[1]=pxm1; xmq[2]=xm.x; xmq[3]=xm.y;
        }

        float qv[2], kv[2], vv[2];
        #pragma unroll
        for (int o = 0; o < 2; o++) {
            float a = 0.f, bk = 0.f, c2 = 0.f;
            #pragma unroll
            for (int i = 0; i < 4; i++) {
                a  += xaq[i]*qwr[o][i];
                bk += xaq[i]*kwr[o][i];
                c2 += xmq[i]*vwr[o][i];
            }
            qv[o] = a; kv[o] = bk; vv[o] = c2;
        }
        size_t base = (((size_t)b*NH_ + h)*S_ + s)*DH_ + dd;
        *(float2*)&g_q[base] = make_float2(qv[0], qv[1]);
        *(float2*)&g_k[base] = make_float2(kv[0], kv[1]);
        *(float2*)&g_v[base] = make_float2(vv[0], vv[1]);
        if (s == S_-1)
            *(float2*)&g_xa_last[b*INNER_ + c0] = make_float2(xa0, xa1);

        #pragma unroll
        for (int o = 0; o < 2; o++) { win[0][o]=win[1][o]; win[1][o]=win[2][o]; win[2][o]=win[3][o]; }
    }
}

// ---------------- K3b: ig/fg gates, float4-vectorized ----------------
__global__ void k3b_gates(const float* __restrict__ igw, const float* __restrict__ igb,
                          const float* __restrict__ fgw, const float* __restrict__ fgb)
{
    int tid = threadIdx.x;
    int lane = tid & 31, w = tid >> 5;
    int blk = blockIdx.x;
    int b = blk >> 4;
    int t0 = (blk & 15) * 32 + w * 4;

    float aI[4][4], aF[4][4];
    #pragma unroll
    for (int r = 0; r < 4; r++)
        #pragma unroll
        for (int g = 0; g < 4; g++) { aI[r][g] = 0.f; aF[r][g] = 0.f; }

    const float* segp[3] = { g_q, g_k, g_v };
    #pragma unroll
    for (int seg = 0; seg < 3; seg++) {
        const float* P = segp[seg];
        #pragma unroll
        for (int c0 = 0; c0 < INNER_; c0 += 128) {
            int cw_ = c0 + lane*4;
            int hh = cw_ >> 8, dd = cw_ & 255;
            float4 wI4[4], wF4[4];
            #pragma unroll
            for (int g = 0; g < 4; g++) {
                wI4[g] = *(const float4*)&igw[g*3072 + seg*1024 + cw_];
                wF4[g] = *(const float4*)&fgw[g*3072 + seg*1024 + cw_];
            }
            size_t rb = (((size_t)b*NH_ + hh)*S_ + t0)*DH_ + dd;
            #pragma unroll
            for (int r = 0; r < 4; r++) {
                float4 val = *(const float4*)&P[rb + (size_t)r*DH_];
                #pragma unroll
                for (int g = 0; g < 4; g++) {
                    aI[r][g] += val.x*wI4[g].x + val.y*wI4[g].y + val.z*wI4[g].z + val.w*wI4[g].w;
                    aF[r][g] += val.x*wF4[g].x + val.y*wF4[g].y + val.z*wF4[g].z + val.w*wF4[g].w;
                }
            }
        }
    }
    #pragma unroll
    for (int r = 0; r < 4; r++) {
        #pragma unroll
        for (int g = 0; g < 4; g++) {
            float sI = aI[r][g], sF = aF[r][g];
            #pragma unroll
            for (int o = 16; o > 0; o >>= 1) {
                sI += __shfl_xor_sync(0xffffffffu, sI, o);
                sF += __shfl_xor_sync(0xffffffffu, sF, o);
            }
            if (lane == 0) {
                int t = t0 + r;
                g_ig[(b*NH_+g)*S_ + t] = sI + igb[g];
                float fgv = sF + fgb[g];
                float lf = (fgv >= 0.f) ? -log1pf(expf(-fgv)) : (fgv - log1pf(expf(fgv)));
                g_lf[(b*NH_+g)*S_ + t] = lf;
            }
        }
    }
}

// ---------------- K4a: qk dots, 4 t-chunks per bh (512 blocks) ----------------
__global__ void k4a_qk()
{
    int bh = blockIdx.x;
    int chunk = blockIdx.y;
    int tid = threadIdx.x;
    int lane = tid & 31, wrp = tid >> 5;

    __shared__ float s_q[DH_];
    s_q[tid] = g_q[((size_t)bh*S_ + (S_-1))*DH_ + tid];
    __syncthreads();

    const float* kb = g_k + (size_t)bh*S_*DH_;
    for (int t = wrp; t < 128; t += 8) {
        int tt = chunk*128 + t;
        const float* kr = kb + (size_t)tt*DH_;
        float p = 0.f;
        #pragma unroll
        for (int i = 0; i < 2; i++) {
            int d = lane*4 + i*128;
            float4 kv = *(const float4*)&kr[d];
            p += s_q[d]*kv.x + s_q[d+1]*kv.y + s_q[d+2]*kv.z + s_q[d+3]*kv.w;
        }
        #pragma unroll
        for (int o = 16; o > 0; o >>= 1) p += __shfl_xor_sync(0xffffffffu, p, o);
        if (lane == 0) g_qk[bh*S_ + tt] = p * 0.0625f;
    }
}

// ---------------- K4w: scan/max/normalize -> weights (128 blocks) ----------------
__global__ void k4w_weights()
{
    int bh = blockIdx.x;
    int tid = threadIdx.x;
    int lane = tid & 31, wrp = tid >> 5;

    __shared__ float red[256];
    __shared__ float wtot[8], woff[8];

    int t0 = 2*tid, t1 = 2*tid + 1;
    float lf0 = g_lf[bh*S_ + t0], lf1 = g_lf[bh*S_ + t1];
    float ig0 = g_ig[bh*S_ + t0], ig1 = g_ig[bh*S_ + t1];

    float v = lf0 + lf1;
    #pragma unroll
    for (int o = 1; o < 32; o <<= 1) {
        float u = __shfl_up_sync(0xffffffffu, v, o);
        if (lane >= o) v += u;
    }
    if (lane == 31) wtot[wrp] = v;
    __syncthreads();
    if (tid < 8) { float t = 0.f; for (int i = 0; i < tid; i++) t += wtot[i]; woff[tid] = t; }
    __syncthreads();
    float cin  = v + woff[wrp];
    float c0   = cin - lf1;
    float total = woff[7] + wtot[7];
    float logd0 = (total - c0)  + ig0;
    float logd1 = (total - cin) + ig1;

    red[tid] = fmaxf(logd0, logd1);
    __syncthreads();
    for (int o = 128; o > 0; o >>= 1) { if (tid < o) red[tid] = fmaxf(red[tid], red[tid+o]); __syncthreads(); }
    float maxd = red[0];
    __syncthreads();

    float d0 = expf(logd0 - maxd), d1 = expf(logd1 - maxd);
    float cm0 = g_qk[bh*S_ + t0]*d0, cm1 = g_qk[bh*S_ + t1]*d1;
    red[tid] = cm0 + cm1;
    __syncthreads();
    for (int o = 128; o > 0; o >>= 1) { if (tid < o) red[tid] += red[tid+o]; __syncthreads(); }
    float csum = red[0];
    float inv = 1.f / (fmaxf(fabsf(csum), expf(-maxd)) + 1e-6f);
    g_w[bh*S_ + t0] = cm0*inv;
    g_w[bh*S_ + t1] = cm1*inv;
}

// ---------------- K4b: hc partial sums over 4 t-chunks (512 blocks) ----------------
__global__ void k4b_hcpart()
{
    int bh = blockIdx.x;
    int chunk = blockIdx.y;
    int tid = threadIdx.x;

    __shared__ float s_w[128];
    if (tid < 128) s_w[tid] = g_w[bh*S_ + chunk*128 + tid];
    __syncthreads();

    const float* vb = g_v + ((size_t)bh*S_ + chunk*128)*DH_;
    float acc = 0.f;
    #pragma unroll 8
    for (int t = 0; t < 128; t++) acc += s_w[t]*vb[(size_t)t*DH_ + tid];
    g_part[(bh*4 + chunk)*DH_ + tid] = acc;
}

// ---------------- K4c: combine partials + head-LN + hs (128 blocks) ----------------
__global__ void k4c_final(const float* __restrict__ onormw, const float* __restrict__ skipw)
{
    int bh = blockIdx.x;
    int b = bh >> 2, h = bh & 3;
    int tid = threadIdx.x;

    __shared__ float red[256];

    float acc = g_part[(bh*4+0)*DH_ + tid] + g_part[(bh*4+1)*DH_ + tid]
              + g_part[(bh*4+2)*DH_ + tid] + g_part[(bh*4+3)*DH_ + tid];

    red[tid] = acc; __syncthreads();
    for (int o = 128; o > 0; o >>= 1) { if (tid < o) red[tid] += red[tid+o]; __syncthreads(); }
    float mu = red[0] * (1.f/DH_);
    __syncthreads();
    red[tid] = acc*acc; __syncthreads();
    for (int o = 128; o > 0; o >>= 1) { if (tid < o) red[tid] += red[tid+o]; __syncthreads(); }
    float var = red[0]*(1.f/DH_) - mu*mu;
    float hn = (acc - mu) * rsqrtf(var + 1e-5f);

    int c = h*DH_ + tid;
    float z = g_z[b*INNER_ + c];
    float hs = (hn*onormw[c] + skipw[c]*g_xa_last[b*INNER_ + c]) * silu_f(z);
    g_hs[b*INNER_ + c] = hs;
}

// ---------------- K5: down-proj (last pos) + post-LN + head ----------------
__global__ void k5_final(const float* __restrict__ wdown, const float* __restrict__ lnpw,
                         const float* __restrict__ fcw, const float* __restrict__ fcb,
                         float* __restrict__ out)
{
    int b = blockIdx.x;
    int tid = threadIdx.x;
    int lane = tid & 31, wrp = tid >> 5;

    __shared__ float s_hs[INNER_];
    __shared__ float s_y[E_];
    __shared__ float red[512];

    s_hs[tid]       = g_hs[b*INNER_ + tid];
    s_hs[tid + 512] = g_hs[b*INNER_ + tid + 512];
    __syncthreads();

    for (int e = wrp; e < E_; e += 16) {
        const float* wr = wdown + (size_t)e*INNER_;
        float p = 0.f;
        #pragma unroll
        for (int c = lane; c < INNER_; c += 32) p += s_hs[c]*wr[c];
        #pragma unroll
        for (int o = 16; o > 0; o >>= 1) p += __shfl_xor_sync(0xffffffffu, p, o);
        if (lane == 0) s_y[e] = g_res_last[b*E_ + e] + p;
    }
    __syncthreads();

    float xv = s_y[tid];
    red[tid] = xv; __syncthreads();
    for (int o = 256; o > 0; o >>= 1) { if (tid < o) red[tid] += red[tid+o]; __syncthreads(); }
    float mean = red[0] * (1.f/E_);
    __syncthreads();
    red[tid] = xv*xv; __syncthreads();
    for (int o = 256; o > 0; o >>= 1) { if (tid < o) red[tid] += red[tid+o]; __syncthreads(); }
    float var = red[0]*(1.f/E_) - mean*mean;
    float xf = (xv - mean) * rsqrtf(var + 1e-5f) * lnpw[tid];
    __syncthreads();
    red[tid] = xf * fcw[tid]; __syncthreads();
    for (int o = 256; o > 0; o >>= 1) { if (tid < o) red[tid] += red[tid+o]; __syncthreads(); }
    if (tid == 0) out[b] = 1.f / (1.f + expf(-(red[0] + fcb[0])));
}

// ---------------- launch ----------------
extern "C" void kernel_launch(void* const* d_in, const int* in_sizes, int n_in,
                              void* d_out, int out_size)
{
    const int*   tokens = (const int*)  d_in[0];
    const float* emb    = (const float*)d_in[1];
    const float* ln1w   = (const float*)d_in[2];
    const float* convw  = (const float*)d_in[3];
    const float* convb  = (const float*)d_in[4];
    const float* wup    = (const float*)d_in[5];
    const float* qw     = (const float*)d_in[6];
    const float* kw     = (const float*)d_in[7];
    const float* vw     = (const float*)d_in[8];
    const float* igw    = (const float*)d_in[9];
    const float* igb    = (const float*)d_in[10];
    const float* fgw    = (const float*)d_in[11];
    const float* fgb    = (const float*)d_in[12];
    const float* onormw = (const float*)d_in[13];
    const float* skipw  = (const float*)d_in[14];
    const float* wdown  = (const float*)d_in[15];
    const float* lnpw   = (const float*)d_in[16];
    const float* fcw    = (const float*)d_in[17];
    const float* fcb    = (const float*)d_in[18];
    float* out = (float*)d_out;

    cudaFuncSetAttribute(k2_gemm_up, cudaFuncAttributeMaxDynamicSharedMemorySize, K2_SMEM);

    k0_round_wup<<<(INNER_*E_)/(256*4), 256>>>(wup);
    k1_embed_ln<<<M_TOK, 256>>>(tokens, emb, ln1w);
    k4z_zproj<<<B_*8, 256>>>(wup);
    dim3 g2(INNER_/TBN, M_TOK/TBM);
    k2_gemm_up<<<g2, 256, K2_SMEM>>>();
    dim3 g3(S_/8, B_, 2);
    k3_conv_qkv<<<g3, 256>>>(convw, convb, qw, kw, vw);
    k3b_gates<<<512, 256>>>(igw, igb, fgw, fgb);
    dim3 g4a(B_*NH_, 4);
    k4a_qk<<<g4a, 256>>>();
    k4w_weights<<<B_*NH_, 256>>>();
    dim3 g4b(B_*NH_, 4);
    k4b_hcpart<<<g4b, 256>>>();
    k4c_final<<<B_*NH_, 256>>>(onormw, skipw);
    k5_final<<<B_, 512>>>(wdown, lnpw, fcw, fcb, out);
}